// round 16
// baseline (speedup 1.0000x reference)
#include <cuda_runtime.h>
#include <cuda_bf16.h>
#include <cstdint>
#include <math.h>

// ---------------- problem constants ----------------
constexpr int LAY = 8;
constexpr int NH  = 16;
constexpr int EMB = 1024;
constexpr int VOC = 32000;
constexpr int SEQ = 1024;
constexpr int BSZ = 2;
constexpr int DFF = 4096;
constexpr int MROWS = BSZ * SEQ;   // 2048
constexpr int QKV = 3 * EMB;       // 3072

// ---------------- scratch (device globals; no cudaMalloc allowed) ----------------
__device__ float g_x [MROWS * EMB];

constexpr size_t WPL = 4ull * EMB * EMB + 2ull * EMB * DFF;
__device__ __align__(16) __nv_bfloat16 g_Whi[LAY * WPL];
__device__ __align__(16) __nv_bfloat16 g_Wlo[LAY * WPL];
__device__ __align__(16) __nv_bfloat16 g_tokhi[(size_t)VOC * EMB];
__device__ __align__(16) __nv_bfloat16 g_toklo[(size_t)VOC * EMB];

__device__ __align__(16) __nv_bfloat16 g_ahi[MROWS * EMB];
__device__ __align__(16) __nv_bfloat16 g_alo[MROWS * EMB];
__device__ __align__(16) __nv_bfloat16 g_qkvh[MROWS * QKV];
__device__ __align__(16) __nv_bfloat16 g_qkvl[MROWS * QKV];
__device__ __align__(16) __nv_bfloat16 g_ohi[MROWS * EMB];
__device__ __align__(16) __nv_bfloat16 g_olo[MROWS * EMB];
__device__ __align__(16) __nv_bfloat16 g_fhi[MROWS * DFF];
__device__ __align__(16) __nv_bfloat16 g_flo[MROWS * DFF];

// per-layer weight offsets inside WPL block (transposed to [N,K]); WQ/WK/WV contiguous
constexpr size_t OFF_WQ = 0;
constexpr size_t OFF_WO = 3ull << 20;
constexpr size_t OFF_W1 = 4ull << 20;
constexpr size_t OFF_W2 = 8ull << 20;

// ---------------- low-level helpers ----------------
__device__ __forceinline__ uint32_t smem_u32(const void* p) {
    uint32_t a;
    asm("{ .reg .u64 t; cvta.to.shared.u64 t, %1; cvt.u32.u64 %0, t; }" : "=r"(a) : "l"(p));
    return a;
}
__device__ __forceinline__ void cp16(uint32_t s, const void* g) {
    asm volatile("cp.async.cg.shared.global [%0], [%1], 16;" :: "r"(s), "l"(g) : "memory");
}
__device__ __forceinline__ void cp_commit() {
    asm volatile("cp.async.commit_group;" ::: "memory");
}
__device__ __forceinline__ void cp_wait1() {
    asm volatile("cp.async.wait_group 1;" ::: "memory");
}
__device__ __forceinline__ void cp_wait0() {
    asm volatile("cp.async.wait_group 0;" ::: "memory");
}
__device__ __forceinline__ void ldm_x4(uint32_t* r, uint32_t a) {
    asm volatile("ldmatrix.sync.aligned.m8n8.x4.shared.b16 {%0,%1,%2,%3}, [%4];"
                 : "=r"(r[0]), "=r"(r[1]), "=r"(r[2]), "=r"(r[3]) : "r"(a));
}
__device__ __forceinline__ void ldm_x4t(uint32_t* r, uint32_t a) {
    asm volatile("ldmatrix.sync.aligned.m8n8.x4.trans.shared.b16 {%0,%1,%2,%3}, [%4];"
                 : "=r"(r[0]), "=r"(r[1]), "=r"(r[2]), "=r"(r[3]) : "r"(a));
}
__device__ __forceinline__ void mma16816(float* d, const uint32_t* a, const uint32_t* b) {
    asm volatile(
        "mma.sync.aligned.m16n8k16.row.col.f32.bf16.bf16.f32 "
        "{%0,%1,%2,%3}, {%4,%5,%6,%7}, {%8,%9}, {%0,%1,%2,%3};"
        : "+f"(d[0]), "+f"(d[1]), "+f"(d[2]), "+f"(d[3])
        : "r"(a[0]), "r"(a[1]), "r"(a[2]), "r"(a[3]), "r"(b[0]), "r"(b[1]));
}
__device__ __forceinline__ uint32_t pack_bf16(float x, float y) {
    __nv_bfloat162 t = __floats2bfloat162_rn(x, y);
    return *reinterpret_cast<uint32_t*>(&t);
}

// ---------------- merged weight conversion (single launch) ----------------
constexpr int CONV_WBLKS = LAY * 6144;
constexpr int CONV_TOKBLKS = (VOC * EMB) / 2048;
constexpr int CONV_BLKS = CONV_WBLKS + CONV_TOKBLKS;

__global__ __launch_bounds__(256) void conv_all_kernel(
    const float* __restrict__ Wq, const float* __restrict__ Wk,
    const float* __restrict__ Wv, const float* __restrict__ Wo,
    const float* __restrict__ W1, const float* __restrict__ W2,
    const float* __restrict__ tok,
    __nv_bfloat16* __restrict__ whi, __nv_bfloat16* __restrict__ wlo,
    __nv_bfloat16* __restrict__ tokhi, __nv_bfloat16* __restrict__ toklo)
{
    const int blk = blockIdx.x;
    const int tid = threadIdx.x;
    if (blk < CONV_WBLKS) {
        const int l = blk / 6144;
        int r = blk % 6144;
        const float* src;
        size_t dst;
        int K, N;
        if (r < 2048) {
            const int m = r >> 9;
            r &= 511;
            src = (m == 0 ? Wq : m == 1 ? Wk : m == 2 ? Wv : Wo) + (size_t)l * EMB * EMB;
            dst = (size_t)l * WPL + (m < 3 ? ((size_t)m << 20) : OFF_WO);
            K = EMB; N = EMB;
        } else if (r < 4096) {
            r -= 2048;
            src = W1 + (size_t)l * EMB * DFF;
            dst = (size_t)l * WPL + OFF_W1;
            K = EMB; N = DFF;
        } else {
            r -= 4096;
            src = W2 + (size_t)l * DFF * EMB;
            dst = (size_t)l * WPL + OFF_W2;
            K = DFF; N = EMB;
        }
        const int ntk = K >> 5;
        const int n0 = (r / ntk) * 64;
        const int k0 = (r % ntk) * 32;
        const int lane = tid & 31, w = tid >> 5;
        const int n  = n0 + w * 8 + (lane >> 2);
        const int kg = k0 + (lane & 3) * 8;

        float v[8];
        #pragma unroll
        for (int i = 0; i < 8; i++)
            v[i] = src[(size_t)(kg + i) * N + n];
        uint32_t hp[4], lp[4];
        #pragma unroll
        for (int i = 0; i < 4; i++) {
            const float a = v[2 * i], b = v[2 * i + 1];
            const float ha = __bfloat162float(__float2bfloat16_rn(a));
            const float hb = __bfloat162float(__float2bfloat16_rn(b));
            hp[i] = pack_bf16(a, b);
            lp[i] = pack_bf16(a - ha, b - hb);
        }
        const size_t o = dst + (size_t)n * K + kg;
        *reinterpret_cast<uint4*>(whi + o) = *reinterpret_cast<uint4*>(hp);
        *reinterpret_cast<uint4*>(wlo + o) = *reinterpret_cast<uint4*>(lp);
    } else {
        const size_t base = (size_t)(blk - CONV_WBLKS) * 2048 + (size_t)tid * 8;
        const float4 a = *reinterpret_cast<const float4*>(tok + base);
        const float4 b = *reinterpret_cast<const float4*>(tok + base + 4);
        uint32_t hp[4], lp[4];
        const float h0 = __bfloat162float(__float2bfloat16_rn(a.x));
        const float h1 = __bfloat162float(__float2bfloat16_rn(a.y));
        const float h2 = __bfloat162float(__float2bfloat16_rn(a.z));
        const float h3 = __bfloat162float(__float2bfloat16_rn(a.w));
        const float h4 = __bfloat162float(__float2bfloat16_rn(b.x));
        const float h5 = __bfloat162float(__float2bfloat16_rn(b.y));
        const float h6 = __bfloat162float(__float2bfloat16_rn(b.z));
        const float h7 = __bfloat162float(__float2bfloat16_rn(b.w));
        hp[0] = pack_bf16(a.x, a.y);  hp[1] = pack_bf16(a.z, a.w);
        hp[2] = pack_bf16(b.x, b.y);  hp[3] = pack_bf16(b.z, b.w);
        lp[0] = pack_bf16(a.x - h0, a.y - h1);
        lp[1] = pack_bf16(a.z - h2, a.w - h3);
        lp[2] = pack_bf16(b.x - h4, b.y - h5);
        lp[3] = pack_bf16(b.z - h6, b.w - h7);
        *reinterpret_cast<uint4*>(tokhi + base) = *reinterpret_cast<uint4*>(hp);
        *reinterpret_cast<uint4*>(toklo + base) = *reinterpret_cast<uint4*>(lp);
    }
}

// ---------------- embedding ----------------
__global__ void embed_kernel(float* __restrict__ x, const int* __restrict__ idx,
                             const float* __restrict__ tok, const float* __restrict__ pos)
{
    int i = blockIdx.x * blockDim.x + threadIdx.x;
    int e  = i & (EMB - 1);
    int bt = i >> 10;
    int t  = bt & (SEQ - 1);
    x[i] = tok[(size_t)idx[bt] * EMB + e] + pos[(size_t)t * EMB + e];
}

// ---------------- layernorm (warp-per-row) with fused bf16 split output ----------------
__global__ __launch_bounds__(256) void ln_split_kernel(
    __nv_bfloat16* __restrict__ ohi, __nv_bfloat16* __restrict__ olo,
    const float* __restrict__ in,
    const float* __restrict__ g, const float* __restrict__ b)
{
    const int row  = blockIdx.x * 8 + (threadIdx.x >> 5);
    const int lane = threadIdx.x & 31;
    const float* xr = in + (size_t)row * EMB;

    float4 v[8];
    float s = 0.f;
    #pragma unroll
    for (int i = 0; i < 8; i++) {
        v[i] = *reinterpret_cast<const float4*>(xr + i * 128 + lane * 4);
        s += v[i].x + v[i].y + v[i].z + v[i].w;
    }
    #pragma unroll
    for (int o = 16; o; o >>= 1) s += __shfl_xor_sync(0xffffffffu, s, o);
    const float m = s * (1.f / EMB);

    float ss = 0.f;
    #pragma unroll
    for (int i = 0; i < 8; i++) {
        const float dx = v[i].x - m, dy = v[i].y - m, dz = v[i].z - m, dw = v[i].w - m;
        ss += dx * dx + dy * dy + dz * dz + dw * dw;
    }
    #pragma unroll
    for (int o = 16; o; o >>= 1) ss += __shfl_xor_sync(0xffffffffu, ss, o);
    const float r = rsqrtf(ss * (1.f / EMB) + 1e-5f);

    #pragma unroll
    for (int i = 0; i < 8; i++) {
        const int c0 = i * 128 + lane * 4;
        const float4 g4 = *reinterpret_cast<const float4*>(g + c0);
        const float4 b4 = *reinterpret_cast<const float4*>(b + c0);
        const float ox = (v[i].x - m) * r * g4.x + b4.x;
        const float oy = (v[i].y - m) * r * g4.y + b4.y;
        const float oz = (v[i].z - m) * r * g4.z + b4.z;
        const float ow = (v[i].w - m) * r * g4.w + b4.w;
        const float hx = __bfloat162float(__float2bfloat16_rn(ox));
        const float hy = __bfloat162float(__float2bfloat16_rn(oy));
        const float hz = __bfloat162float(__float2bfloat16_rn(oz));
        const float hw = __bfloat162float(__float2bfloat16_rn(ow));
        uint32_t hp[2], lp[2];
        hp[0] = pack_bf16(ox, oy);  hp[1] = pack_bf16(oz, ow);
        lp[0] = pack_bf16(ox - hx, oy - hy);
        lp[1] = pack_bf16(oz - hz, ow - hw);
        *reinterpret_cast<uint2*>(ohi + (size_t)row * EMB + c0) = *reinterpret_cast<uint2*>(hp);
        *reinterpret_cast<uint2*>(olo + (size_t)row * EMB + c0) = *reinterpret_cast<uint2*>(lp);
    }
}

// ---------------- bf16x3 GEMM: 128x128 tile, BK=32, XOR-swizzled 64B rows ----------------
// 3 stages x 32KB = 96KB smem -> 2 CTAs/SM. 256 threads, __launch_bounds__(256,2).
// swizzle: 16B-chunk c of row r stored at r*64 + ((c ^ ((r>>1)&3)) * 16). k-step = offset^32.
constexpr int MAT3 = 128 * 64;          // 8192 bytes per matrix per stage
constexpr int STG3 = 4 * MAT3;          // 32768
constexpr int GEMM_SMEM = 3 * STG3;     // 98304

template<bool BIAS, bool RELU, bool RES, bool SPLIT>
__global__ __launch_bounds__(256, 2) void mma_gemm(
    const __nv_bfloat16* __restrict__ Ahi, const __nv_bfloat16* __restrict__ Alo,
    const __nv_bfloat16* __restrict__ Bhi, const __nv_bfloat16* __restrict__ Blo,
    const float* __restrict__ bias, const float* __restrict__ res,
    float* __restrict__ C,
    __nv_bfloat16* __restrict__ Chi, __nv_bfloat16* __restrict__ Clo,
    int N, int K, int ntn, int ntiles)
{
    extern __shared__ char sm[];
    const int tid  = threadIdx.x;
    const int lane = tid & 31, wid = tid >> 5;
    const int wm = wid >> 1, wn = wid & 1;       // 4 x 2 warp grid, warp tile 32x64
    const uint32_t smb = smem_u32(sm);
    const int NC = K >> 5;

    // ldmatrix offsets for ks=0 (XOR 32 gives ks=1)
    const int rA = lane & 15, cA = lane >> 4;
    uint32_t offA[2];
    #pragma unroll
    for (int i = 0; i < 2; i++) {
        const int row = wm * 32 + i * 16 + rA;
        offA[i] = (uint32_t)(row * 64 + ((cA ^ ((row >> 1) & 3)) * 16));
    }
    const int rB = (lane & 7) | ((lane >> 4) << 3), cB = (lane >> 3) & 1;
    uint32_t offB[4];
    #pragma unroll
    for (int j = 0; j < 4; j++) {
        const int row = wn * 64 + j * 16 + rB;
        offB[j] = (uint32_t)(row * 64 + ((cB ^ ((row >> 1) & 3)) * 16));
    }

    // loader per-thread positions (2 chunks per matrix)
    const int lrow0 = tid >> 2,           lc0 = tid & 3;
    const int lrow1 = (tid + 256) >> 2,   lc1 = (tid + 256) & 3;
    const uint32_t lso0 = (uint32_t)(lrow0 * 64 + ((lc0 ^ ((lrow0 >> 1) & 3)) * 16));
    const uint32_t lso1 = (uint32_t)(lrow1 * 64 + ((lc1 ^ ((lrow1 >> 1) & 3)) * 16));

    const int g2 = lane >> 2, t2 = lane & 3;

    for (int t = blockIdx.x; t < ntiles; t += gridDim.x) {
        const int bm0 = (t / ntn) * 128;
        const int bn0 = (t % ntn) * 128;

        float acc[2][8][4];
        #pragma unroll
        for (int i = 0; i < 2; i++)
            #pragma unroll
            for (int j = 0; j < 8; j++)
                #pragma unroll
                for (int q = 0; q < 4; q++) acc[i][j][q] = 0.f;

        auto issue = [&](int c) {
            const int k0 = c << 5;
            const uint32_t st = smb + (c % 3) * STG3;
            {
                const size_t ga = (size_t)(bm0 + lrow0) * K + k0 + lc0 * 8;
                const size_t gb = (size_t)(bn0 + lrow0) * K + k0 + lc0 * 8;
                cp16(st + lso0,            Ahi + ga);
                cp16(st + MAT3 + lso0,     Alo + ga);
                cp16(st + 2 * MAT3 + lso0, Bhi + gb);
                cp16(st + 3 * MAT3 + lso0, Blo + gb);
            }
            {
                const size_t ga = (size_t)(bm0 + lrow1) * K + k0 + lc1 * 8;
                const size_t gb = (size_t)(bn0 + lrow1) * K + k0 + lc1 * 8;
                cp16(st + lso1,            Ahi + ga);
                cp16(st + MAT3 + lso1,     Alo + ga);
                cp16(st + 2 * MAT3 + lso1, Bhi + gb);
                cp16(st + 3 * MAT3 + lso1, Blo + gb);
            }
            cp_commit();
        };

        issue(0);
        issue(1);

        for (int c = 0; c < NC; c++) {
            if (c + 2 < NC) cp_wait1(); else cp_wait0();
            __syncthreads();
            if (c + 2 < NC) issue(c + 2);

            const uint32_t st = smb + (c % 3) * STG3;
            #pragma unroll
            for (int ks = 0; ks < 2; ks++) {
                const uint32_t kx = ks * 32;
                uint32_t ah[2][4], al[2][4];
                #pragma unroll
                for (int i = 0; i < 2; i++) {
                    ldm_x4(ah[i], st + (offA[i] ^ kx));
                    ldm_x4(al[i], st + MAT3 + (offA[i] ^ kx));
                }
                #pragma unroll
                for (int j4 = 0; j4 < 4; j4++) {
                    uint32_t bh[4], bl[4];
                    ldm_x4(bh, st + 2 * MAT3 + (offB[j4] ^ kx));
                    ldm_x4(bl, st + 3 * MAT3 + (offB[j4] ^ kx));
                    #pragma unroll
                    for (int i = 0; i < 2; i++)
                        #pragma unroll
                        for (int jj = 0; jj < 2; jj++) {
                            const int j = j4 * 2 + jj, hh = jj * 2;
                            mma16816(acc[i][j], ah[i], &bh[hh]);
                            mma16816(acc[i][j], ah[i], &bl[hh]);
                            mma16816(acc[i][j], al[i], &bh[hh]);
                        }
                }
            }
        }

        #pragma unroll
        for (int i = 0; i < 2; i++) {
            #pragma unroll
            for (int j = 0; j < 8; j++) {
                const int row0 = bm0 + wm * 32 + i * 16 + g2;
                const int col  = bn0 + wn * 64 + j * 8 + t2 * 2;
                #pragma unroll
                for (int half = 0; half < 2; half++) {
                    const int row = row0 + half * 8;
                    float vx = acc[i][j][half * 2 + 0];
                    float vy = acc[i][j][half * 2 + 1];
                    if (BIAS) { vx += bias[col]; vy += bias[col + 1]; }
                    if (RES) {
                        const float2 rr = *reinterpret_cast<const float2*>(res + (size_t)row * N + col);
                        vx += rr.x; vy += rr.y;
                    }
                    if (RELU) { vx = fmaxf(vx, 0.f); vy = fmaxf(vy, 0.f); }
                    if (SPLIT) {
                        float hx = __bfloat162float(__float2bfloat16_rn(vx));
                        float hy = __bfloat162float(__float2bfloat16_rn(vy));
                        *reinterpret_cast<uint32_t*>(Chi + (size_t)row * N + col) = pack_bf16(vx, vy);
                        *reinterpret_cast<uint32_t*>(Clo + (size_t)row * N + col) = pack_bf16(vx - hx, vy - hy);
                    } else {
                        float2 v; v.x = vx; v.y = vy;
                        *reinterpret_cast<float2*>(C + (size_t)row * N + col) = v;
                    }
                }
            }
        }
        __syncthreads();   // protect smem before next tile's prologue
    }
}

// ---------------- tensor-core flash attention (bf16x3, causal), packed QKV ----------------
constexpr int AP = 72;
constexpr int AQ_HI = 0;
constexpr int AQ_LO = 128 * AP;
constexpr int AST0  = 2 * 128 * AP;
constexpr int AMAT  = 64 * AP;
constexpr int ASTAGE = 4 * AMAT;
constexpr int ATTN_SMEM = (AST0 + 2 * ASTAGE) * 2;   // 110,592 bytes

__global__ __launch_bounds__(128) void attn_tc_kernel(
    const __nv_bfloat16* __restrict__ QKVh, const __nv_bfloat16* __restrict__ QKVl,
    __nv_bfloat16* __restrict__ Ohi, __nv_bfloat16* __restrict__ Olo)
{
    extern __shared__ __nv_bfloat16 smb16[];
    const uint32_t smb = smem_u32(smb16);

    const int qt = gridDim.x - 1 - blockIdx.x;
    const int bh = blockIdx.y;
    const int b  = bh >> 4;
    const int h  = bh & 15;
    const int tid = threadIdx.x;
    const int lane = tid & 31, wid = tid >> 5;
    const int g2 = lane >> 2, t2 = lane & 3;

    const size_t rowbase = (size_t)(b * SEQ + qt * 128);
    const int hoff = h * 64;

    #pragma unroll
    for (int it = 0; it < 8; it++) {
        int idx = tid + it * 128;
        int row = idx >> 3, c8 = (idx & 7) * 8;
        const size_t gq = (rowbase + row) * QKV + hoff + c8;
        *reinterpret_cast<uint4*>(smb16 + AQ_HI + row * AP + c8) =
            *reinterpret_cast<const uint4*>(QKVh + gq);
        *reinterpret_cast<uint4*>(smb16 + AQ_LO + row * AP + c8) =
            *reinterpret_cast<const uint4*>(QKVl + gq);
    }

    auto issue_kv = [&](int jt) {
        const uint32_t st = smb + (AST0 + (jt & 1) * ASTAGE) * 2;
        const size_t kb = (size_t)(b * SEQ + jt * 64);
        #pragma unroll
        for (int it = 0; it < 4; it++) {
            int idx = tid + it * 128;
            int row = idx >> 3, c8 = (idx & 7) * 8;
            const size_t g = (kb + row) * QKV + hoff + c8;
            const uint32_t so = (uint32_t)((row * AP + c8) * 2);
            cp16(st + so,            QKVh + g + EMB);
            cp16(st + AMAT * 2 + so, QKVl + g + EMB);
            cp16(st + AMAT * 4 + so, QKVh + g + 2 * EMB);
            cp16(st + AMAT * 6 + so, QKVl + g + 2 * EMB);
        }
        cp_commit();
    };

    const int rA = lane & 15, cA = lane >> 4;
    uint32_t qoff[2];
    #pragma unroll
    for (int i = 0; i < 2; i++)
        qoff[i] = (uint32_t)(((wid * 32 + i * 16 + rA) * AP + cA * 8) * 2);
    const int rB = (lane & 7) | ((lane >> 4) << 3), cB = (lane >> 3) & 1;
    uint32_t koff[4];
    #pragma unroll
    for (int j = 0; j < 4; j++)
        koff[j] = (uint32_t)(((j * 16 + rB) * AP + cB * 8) * 2);
    const uint32_t voff_row = (uint32_t)(rA * AP + cA * 8) * 2;

    float oacc[2][8][4];
    float mstat[4], lstat[4];
    #pragma unroll
    for (int i = 0; i < 2; i++)
        #pragma unroll
        for (int j = 0; j < 8; j++)
            #pragma unroll
            for (int q = 0; q < 4; q++) oacc[i][j][q] = 0.f;
    #pragma unroll
    for (int t = 0; t < 4; t++) { mstat[t] = -1e30f; lstat[t] = 0.f; }

    const int NT = 2 * qt + 2;
    issue_kv(0);

    for (int jt = 0; jt < NT; jt++) {
        if (jt + 1 < NT) { issue_kv(jt + 1); cp_wait1(); }
        else cp_wait0();
        __syncthreads();

        const uint32_t st = smb + (AST0 + (jt & 1) * ASTAGE) * 2;

        float sacc[2][8][4];
        #pragma unroll
        for (int i = 0; i < 2; i++)
            #pragma unroll
            for (int j = 0; j < 8; j++)
                #pragma unroll
                for (int q = 0; q < 4; q++) sacc[i][j][q] = 0.f;

        #pragma unroll
        for (int ks = 0; ks < 4; ks++) {
            const uint32_t kadd = ks * 32;
            uint32_t qh[2][4], ql[2][4], kh[4][4], kl[4][4];
            #pragma unroll
            for (int i = 0; i < 2; i++) {
                ldm_x4(qh[i], smb + AQ_HI * 2 + qoff[i] + kadd);
                ldm_x4(ql[i], smb + AQ_LO * 2 + qoff[i] + kadd);
            }
            #pragma unroll
            for (int j = 0; j < 4; j++) {
                ldm_x4(kh[j], st + koff[j] + kadd);
                ldm_x4(kl[j], st + AMAT * 2 + koff[j] + kadd);
            }
            #pragma unroll
            for (int i = 0; i < 2; i++)
                #pragma unroll
                for (int j = 0; j < 8; j++) {
                    const int j4 = j >> 1, hh = (j & 1) * 2;
                    mma16816(sacc[i][j], qh[i], &kh[j4][hh]);
                    mma16816(sacc[i][j], qh[i], &kl[j4][hh]);
                    mma16816(sacc[i][j], ql[i], &kh[j4][hh]);
                }
        }

        const bool need_mask = (jt * 64 + 63) > (qt * 128);
        #pragma unroll
        for (int i = 0; i < 2; i++) {
            #pragma unroll
            for (int j = 0; j < 8; j++) {
                #pragma unroll
                for (int q = 0; q < 4; q++) {
                    float s = sacc[i][j][q] * 0.125f;
                    if (need_mask) {
                        const int row = qt * 128 + wid * 32 + i * 16 + g2 + (q >> 1) * 8;
                        const int col = jt * 64 + j * 8 + t2 * 2 + (q & 1);
                        if (col > row) s = -1e30f;
                    }
                    sacc[i][j][q] = s;
                }
            }
        }

        float alpha[4];
        #pragma unroll
        for (int i = 0; i < 2; i++) {
            #pragma unroll
            for (int half = 0; half < 2; half++) {
                const int t = i * 2 + half;
                float mx = -1e30f;
                #pragma unroll
                for (int j = 0; j < 8; j++)
                    mx = fmaxf(mx, fmaxf(sacc[i][j][half * 2], sacc[i][j][half * 2 + 1]));
                mx = fmaxf(mx, __shfl_xor_sync(0xffffffffu, mx, 1));
                mx = fmaxf(mx, __shfl_xor_sync(0xffffffffu, mx, 2));
                const float mnew = fmaxf(mstat[t], mx);
                alpha[t] = exp2f((mstat[t] - mnew) * 1.4426950408889634f);
                mstat[t] = mnew;
                float rs = 0.f;
                #pragma unroll
                for (int j = 0; j < 8; j++) {
                    float p0 = exp2f((sacc[i][j][half * 2]     - mnew) * 1.4426950408889634f);
                    float p1 = exp2f((sacc[i][j][half * 2 + 1] - mnew) * 1.4426950408889634f);
                    sacc[i][j][half * 2] = p0;
                    sacc[i][j][half * 2 + 1] = p1;
                    rs += p0 + p1;
                }
                rs += __shfl_xor_sync(0xffffffffu, rs, 1);
                rs += __shfl_xor_sync(0xffffffffu, rs, 2);
                lstat[t] = lstat[t] * alpha[t] + rs;
                #pragma unroll
                for (int j = 0; j < 8; j++) {
                    oacc[i][j][half * 2]     *= alpha[t];
                    oacc[i][j][half * 2 + 1] *= alpha[t];
                }
            }
        }

        #pragma unroll
        for (int kk = 0; kk < 4; kk++) {
            uint32_t ph[2][4], pl[2][4];
            #pragma unroll
            for (int i = 0; i < 2; i++) {
                const int j0 = 2 * kk, j1 = j0 + 1;
                const float c0 = sacc[i][j0][0], c1 = sacc[i][j0][1];
                const float c2 = sacc[i][j0][2], c3 = sacc[i][j0][3];
                const float d0 = sacc[i][j1][0], d1 = sacc[i][j1][1];
                const float d2 = sacc[i][j1][2], d3 = sacc[i][j1][3];
                ph[i][0] = pack_bf16(c0, c1);
                ph[i][1] = pack_bf16(c2, c3);
                ph[i][2] = pack_bf16(d0, d1);
                ph[i][3] = pack_bf16(d2, d3);
                const float h0 = __bfloat162float(__float2bfloat16_rn(c0));
                const float h1 = __bfloat162float(__float2bfloat16_rn(c1));
                const float h2 = __bfloat162float(__float2bfloat16_rn(c2));
                const float h3 = __bfloat162float(__float2bfloat16_rn(c3));
                const float e0 = __bfloat162float(__float2bfloat16_rn(d0));
                const float e1 = __bfloat162float(__float2bfloat16_rn(d1));
                const float e2 = __bfloat162float(__float2bfloat16_rn(d2));
                const float e3 = __bfloat162float(__float2bfloat16_rn(d3));
                pl[i][0] = pack_bf16(c0 - h0, c1 - h1);
                pl[i][1] = pack_bf16(c2 - h2, c3 - h3);
                pl[i][2] = pack_bf16(d0 - e0, d1 - e1);
                pl[i][3] = pack_bf16(d2 - e2, d3 - e3);
            }
            uint32_t vh[4][4], vl[4][4];
            const uint32_t vrow = (uint32_t)((kk * 16) * AP * 2);
            #pragma unroll
            for (int dgrp = 0; dgrp < 4; dgrp++) {
                const uint32_t va = st + AMAT * 4 + vrow + voff_row + (uint32_t)(dgrp * 16 * 2);
                ldm_x4t(vh[dgrp], va);
                ldm_x4t(vl[dgrp], va + AMAT * 2);
            }
            #pragma unroll
            for (int i = 0; i < 2; i++)
                #pragma unroll
                for (int jd = 0; jd < 8; jd++) {
                    const int vg = jd >> 1, sel = (jd & 1) * 2;
                    mma16816(oacc[i][jd], ph[i], &vh[vg][sel]);
                    mma16816(oacc[i][jd], ph[i], &vl[vg][sel]);
                    mma16816(oacc[i][jd], pl[i], &vh[vg][sel]);
                }
        }
        __syncthreads();
    }

    #pragma unroll
    for (int i = 0; i < 2; i++) {
        #pragma unroll
        for (int half = 0; half < 2; half++) {
            const int t = i * 2 + half;
            const float inv = 1.f / lstat[t];
            const size_t row = rowbase + wid * 32 + i * 16 + g2 + half * 8;
            #pragma unroll
            for (int jd = 0; jd < 8; jd++) {
                const int col = hoff + jd * 8 + t2 * 2;
                const float vx = oacc[i][jd][half * 2]     * inv;
                const float vy = oacc[i][jd][half * 2 + 1] * inv;
                const float hx = __bfloat162float(__float2bfloat16_rn(vx));
                const float hy = __bfloat162float(__float2bfloat16_rn(vy));
                *reinterpret_cast<uint32_t*>(Ohi + row * EMB + col) = pack_bf16(vx, vy);
                *reinterpret_cast<uint32_t*>(Olo + row * EMB + col) = pack_bf16(vx - hx, vy - hy);
            }
        }
    }
}

// ---------------- host orchestration ----------------
static inline int gclamp2(int ntiles) { return ntiles < 296 ? ntiles : 296; }

extern "C" void kernel_launch(void* const* d_in, const int* in_sizes, int n_in,
                              void* d_out, int out_size)
{
    const int*   idx  = (const int*)  d_in[0];
    const float* tok  = (const float*)d_in[1];
    const float* pos  = (const float*)d_in[2];
    const float* Wq   = (const float*)d_in[3];
    const float* Wk   = (const float*)d_in[4];
    const float* Wv   = (const float*)d_in[5];
    const float* Wo   = (const float*)d_in[6];
    const float* bo   = (const float*)d_in[7];
    const float* W1   = (const float*)d_in[8];
    const float* b1   = (const float*)d_in[9];
    const float* W2   = (const float*)d_in[10];
    const float* b2   = (const float*)d_in[11];
    const float* ln1g = (const float*)d_in[12];
    const float* ln1b = (const float*)d_in[13];
    const float* ln2g = (const float*)d_in[14];
    const float* ln2b = (const float*)d_in[15];
    const float* lnfg = (const float*)d_in[16];
    const float* lnfb = (const float*)d_in[17];
    const float* lmb  = (const float*)d_in[18];
    float* out = (float*)d_out;

    float* x;
    __nv_bfloat16 *whi, *wlo, *tokhi, *toklo;
    __nv_bfloat16 *ahi, *alo, *qkvh, *qkvl, *ohi, *olo, *fhi, *flo;
    cudaGetSymbolAddress((void**)&x,  g_x);
    cudaGetSymbolAddress((void**)&whi, g_Whi);
    cudaGetSymbolAddress((void**)&wlo, g_Wlo);
    cudaGetSymbolAddress((void**)&tokhi, g_tokhi);
    cudaGetSymbolAddress((void**)&toklo, g_toklo);
    cudaGetSymbolAddress((void**)&ahi, g_ahi);
    cudaGetSymbolAddress((void**)&alo, g_alo);
    cudaGetSymbolAddress((void**)&qkvh, g_qkvh);
    cudaGetSymbolAddress((void**)&qkvl, g_qkvl);
    cudaGetSymbolAddress((void**)&ohi, g_ohi);
    cudaGetSymbolAddress((void**)&olo, g_olo);
    cudaGetSymbolAddress((void**)&fhi, g_fhi);
    cudaGetSymbolAddress((void**)&flo, g_flo);

    cudaFuncSetAttribute(attn_tc_kernel, cudaFuncAttributeMaxDynamicSharedMemorySize, ATTN_SMEM);
    cudaFuncSetAttribute(mma_gemm<false,false,false,true>, cudaFuncAttributeMaxDynamicSharedMemorySize, GEMM_SMEM);
    cudaFuncSetAttribute(mma_gemm<true,false,true,false>,  cudaFuncAttributeMaxDynamicSharedMemorySize, GEMM_SMEM);
    cudaFuncSetAttribute(mma_gemm<true,true,false,true>,   cudaFuncAttributeMaxDynamicSharedMemorySize, GEMM_SMEM);
    cudaFuncSetAttribute(mma_gemm<true,false,false,false>, cudaFuncAttributeMaxDynamicSharedMemorySize, GEMM_SMEM);

    // [0] merged weight + tok conversion
    conv_all_kernel<<<CONV_BLKS, 256>>>(Wq, Wk, Wv, Wo, W1, W2, tok,
                                        whi, wlo, tokhi, toklo);
    // [1] embedding
    embed_kernel<<<(MROWS * EMB) / 256, 256>>>(x, idx, tok, pos);

    const int ntQKV = (MROWS / 128) * (QKV / 128);     // 384
    const int ntE   = (MROWS / 128) * (EMB / 128);     // 128
    const int ntF   = (MROWS / 128) * (DFF / 128);     // 512
    const int ntV   = (MROWS / 128) * (VOC / 128);     // 4000
    const dim3 gattn(SEQ / 128, BSZ * NH);

    for (int l = 0; l < LAY; l++) {
        const size_t wb = (size_t)l * WPL;
        ln_split_kernel<<<MROWS / 8, 256>>>(ahi, alo, x, ln1g + (size_t)l * EMB, ln1b + (size_t)l * EMB);
        mma_gemm<false,false,false,true><<<gclamp2(ntQKV), 256, GEMM_SMEM>>>(
            ahi, alo, whi + wb + OFF_WQ, wlo + wb + OFF_WQ, nullptr, nullptr, nullptr,
            qkvh, qkvl, QKV, EMB, QKV / 128, ntQKV);
        attn_tc_kernel<<<gattn, 128, ATTN_SMEM>>>(qkvh, qkvl, ohi, olo);
        mma_gemm<true,false,true,false><<<gclamp2(ntE), 256, GEMM_SMEM>>>(
            ohi, olo, whi + wb + OFF_WO, wlo + wb + OFF_WO, bo + (size_t)l * EMB, x, x,
            nullptr, nullptr, EMB, EMB, EMB / 128, ntE);
        ln_split_kernel<<<MROWS / 8, 256>>>(ahi, alo, x, ln2g + (size_t)l * EMB, ln2b + (size_t)l * EMB);
        mma_gemm<true,true,false,true><<<gclamp2(ntF), 256, GEMM_SMEM>>>(
            ahi, alo, whi + wb + OFF_W1, wlo + wb + OFF_W1, b1 + (size_t)l * DFF, nullptr, nullptr,
            fhi, flo, DFF, EMB, DFF / 128, ntF);
        mma_gemm<true,false,true,false><<<gclamp2(ntE), 256, GEMM_SMEM>>>(
            fhi, flo, whi + wb + OFF_W2, wlo + wb + OFF_W2, b2 + (size_t)l * EMB, x, x,
            nullptr, nullptr, EMB, DFF, EMB / 128, ntE);
    }

    ln_split_kernel<<<MROWS / 8, 256>>>(ahi, alo, x, lnfg, lnfb);
    mma_gemm<true,false,false,false><<<gclamp2(ntV), 256, GEMM_SMEM>>>(
        ahi, alo, tokhi, toklo, lmb, nullptr, out,
        nullptr, nullptr, VOC, EMB, VOC / 128, ntV);
}

// round 17
// speedup vs baseline: 1.0627x; 1.0627x over previous
#include <cuda_runtime.h>
#include <cuda_bf16.h>
#include <cstdint>
#include <math.h>

// ---------------- problem constants ----------------
constexpr int LAY = 8;
constexpr int NH  = 16;
constexpr int EMB = 1024;
constexpr int VOC = 32000;
constexpr int SEQ = 1024;
constexpr int BSZ = 2;
constexpr int DFF = 4096;
constexpr int MROWS = BSZ * SEQ;   // 2048
constexpr int QKV = 3 * EMB;       // 3072

// ---------------- scratch (device globals; no cudaMalloc allowed) ----------------
__device__ float g_x [MROWS * EMB];

constexpr size_t WPL = 4ull * EMB * EMB + 2ull * EMB * DFF;
__device__ __align__(16) __nv_bfloat16 g_Whi[LAY * WPL];
__device__ __align__(16) __nv_bfloat16 g_Wlo[LAY * WPL];
__device__ __align__(16) __nv_bfloat16 g_tokhi[(size_t)VOC * EMB];
__device__ __align__(16) __nv_bfloat16 g_toklo[(size_t)VOC * EMB];

__device__ __align__(16) __nv_bfloat16 g_ahi[MROWS * EMB];
__device__ __align__(16) __nv_bfloat16 g_alo[MROWS * EMB];
__device__ __align__(16) __nv_bfloat16 g_qkvh[MROWS * QKV];
__device__ __align__(16) __nv_bfloat16 g_qkvl[MROWS * QKV];
__device__ __align__(16) __nv_bfloat16 g_ohi[MROWS * EMB];
__device__ __align__(16) __nv_bfloat16 g_olo[MROWS * EMB];
__device__ __align__(16) __nv_bfloat16 g_fhi[MROWS * DFF];
__device__ __align__(16) __nv_bfloat16 g_flo[MROWS * DFF];

// per-layer weight offsets inside WPL block (transposed to [N,K]); WQ/WK/WV contiguous
constexpr size_t OFF_WQ = 0;
constexpr size_t OFF_WO = 3ull << 20;
constexpr size_t OFF_W1 = 4ull << 20;
constexpr size_t OFF_W2 = 8ull << 20;

// ---------------- low-level helpers ----------------
__device__ __forceinline__ uint32_t smem_u32(const void* p) {
    uint32_t a;
    asm("{ .reg .u64 t; cvta.to.shared.u64 t, %1; cvt.u32.u64 %0, t; }" : "=r"(a) : "l"(p));
    return a;
}
__device__ __forceinline__ void cp16(uint32_t s, const void* g) {
    asm volatile("cp.async.cg.shared.global [%0], [%1], 16;" :: "r"(s), "l"(g) : "memory");
}
__device__ __forceinline__ void cp_commit() {
    asm volatile("cp.async.commit_group;" ::: "memory");
}
__device__ __forceinline__ void cp_wait1() {
    asm volatile("cp.async.wait_group 1;" ::: "memory");
}
__device__ __forceinline__ void cp_wait0() {
    asm volatile("cp.async.wait_group 0;" ::: "memory");
}
__device__ __forceinline__ void ldm_x4(uint32_t* r, uint32_t a) {
    asm volatile("ldmatrix.sync.aligned.m8n8.x4.shared.b16 {%0,%1,%2,%3}, [%4];"
                 : "=r"(r[0]), "=r"(r[1]), "=r"(r[2]), "=r"(r[3]) : "r"(a));
}
__device__ __forceinline__ void ldm_x4t(uint32_t* r, uint32_t a) {
    asm volatile("ldmatrix.sync.aligned.m8n8.x4.trans.shared.b16 {%0,%1,%2,%3}, [%4];"
                 : "=r"(r[0]), "=r"(r[1]), "=r"(r[2]), "=r"(r[3]) : "r"(a));
}
__device__ __forceinline__ void mma16816(float* d, const uint32_t* a, const uint32_t* b) {
    asm volatile(
        "mma.sync.aligned.m16n8k16.row.col.f32.bf16.bf16.f32 "
        "{%0,%1,%2,%3}, {%4,%5,%6,%7}, {%8,%9}, {%0,%1,%2,%3};"
        : "+f"(d[0]), "+f"(d[1]), "+f"(d[2]), "+f"(d[3])
        : "r"(a[0]), "r"(a[1]), "r"(a[2]), "r"(a[3]), "r"(b[0]), "r"(b[1]));
}
__device__ __forceinline__ uint32_t pack_bf16(float x, float y) {
    __nv_bfloat162 t = __floats2bfloat162_rn(x, y);
    return *reinterpret_cast<uint32_t*>(&t);
}

// ---------------- merged weight conversion (single launch) ----------------
constexpr int CONV_WBLKS = LAY * 6144;
constexpr int CONV_TOKBLKS = (VOC * EMB) / 2048;
constexpr int CONV_BLKS = CONV_WBLKS + CONV_TOKBLKS;

__global__ __launch_bounds__(256) void conv_all_kernel(
    const float* __restrict__ Wq, const float* __restrict__ Wk,
    const float* __restrict__ Wv, const float* __restrict__ Wo,
    const float* __restrict__ W1, const float* __restrict__ W2,
    const float* __restrict__ tok,
    __nv_bfloat16* __restrict__ whi, __nv_bfloat16* __restrict__ wlo,
    __nv_bfloat16* __restrict__ tokhi, __nv_bfloat16* __restrict__ toklo)
{
    const int blk = blockIdx.x;
    const int tid = threadIdx.x;
    if (blk < CONV_WBLKS) {
        const int l = blk / 6144;
        int r = blk % 6144;
        const float* src;
        size_t dst;
        int K, N;
        if (r < 2048) {
            const int m = r >> 9;
            r &= 511;
            src = (m == 0 ? Wq : m == 1 ? Wk : m == 2 ? Wv : Wo) + (size_t)l * EMB * EMB;
            dst = (size_t)l * WPL + (m < 3 ? ((size_t)m << 20) : OFF_WO);
            K = EMB; N = EMB;
        } else if (r < 4096) {
            r -= 2048;
            src = W1 + (size_t)l * EMB * DFF;
            dst = (size_t)l * WPL + OFF_W1;
            K = EMB; N = DFF;
        } else {
            r -= 4096;
            src = W2 + (size_t)l * DFF * EMB;
            dst = (size_t)l * WPL + OFF_W2;
            K = DFF; N = EMB;
        }
        const int ntk = K >> 5;
        const int n0 = (r / ntk) * 64;
        const int k0 = (r % ntk) * 32;
        const int lane = tid & 31, w = tid >> 5;
        const int n  = n0 + w * 8 + (lane >> 2);
        const int kg = k0 + (lane & 3) * 8;

        float v[8];
        #pragma unroll
        for (int i = 0; i < 8; i++)
            v[i] = src[(size_t)(kg + i) * N + n];
        uint32_t hp[4], lp[4];
        #pragma unroll
        for (int i = 0; i < 4; i++) {
            const float a = v[2 * i], b = v[2 * i + 1];
            const float ha = __bfloat162float(__float2bfloat16_rn(a));
            const float hb = __bfloat162float(__float2bfloat16_rn(b));
            hp[i] = pack_bf16(a, b);
            lp[i] = pack_bf16(a - ha, b - hb);
        }
        const size_t o = dst + (size_t)n * K + kg;
        *reinterpret_cast<uint4*>(whi + o) = *reinterpret_cast<uint4*>(hp);
        *reinterpret_cast<uint4*>(wlo + o) = *reinterpret_cast<uint4*>(lp);
    } else {
        const size_t base = (size_t)(blk - CONV_WBLKS) * 2048 + (size_t)tid * 8;
        const float4 a = *reinterpret_cast<const float4*>(tok + base);
        const float4 b = *reinterpret_cast<const float4*>(tok + base + 4);
        uint32_t hp[4], lp[4];
        const float h0 = __bfloat162float(__float2bfloat16_rn(a.x));
        const float h1 = __bfloat162float(__float2bfloat16_rn(a.y));
        const float h2 = __bfloat162float(__float2bfloat16_rn(a.z));
        const float h3 = __bfloat162float(__float2bfloat16_rn(a.w));
        const float h4 = __bfloat162float(__float2bfloat16_rn(b.x));
        const float h5 = __bfloat162float(__float2bfloat16_rn(b.y));
        const float h6 = __bfloat162float(__float2bfloat16_rn(b.z));
        const float h7 = __bfloat162float(__float2bfloat16_rn(b.w));
        hp[0] = pack_bf16(a.x, a.y);  hp[1] = pack_bf16(a.z, a.w);
        hp[2] = pack_bf16(b.x, b.y);  hp[3] = pack_bf16(b.z, b.w);
        lp[0] = pack_bf16(a.x - h0, a.y - h1);
        lp[1] = pack_bf16(a.z - h2, a.w - h3);
        lp[2] = pack_bf16(b.x - h4, b.y - h5);
        lp[3] = pack_bf16(b.z - h6, b.w - h7);
        *reinterpret_cast<uint4*>(tokhi + base) = *reinterpret_cast<uint4*>(hp);
        *reinterpret_cast<uint4*>(toklo + base) = *reinterpret_cast<uint4*>(lp);
    }
}

// ---------------- embedding ----------------
__global__ void embed_kernel(float* __restrict__ x, const int* __restrict__ idx,
                             const float* __restrict__ tok, const float* __restrict__ pos)
{
    int i = blockIdx.x * blockDim.x + threadIdx.x;
    int e  = i & (EMB - 1);
    int bt = i >> 10;
    int t  = bt & (SEQ - 1);
    x[i] = tok[(size_t)idx[bt] * EMB + e] + pos[(size_t)t * EMB + e];
}

// ---------------- layernorm (warp-per-row) with fused bf16 split output ----------------
__global__ __launch_bounds__(256) void ln_split_kernel(
    __nv_bfloat16* __restrict__ ohi, __nv_bfloat16* __restrict__ olo,
    const float* __restrict__ in,
    const float* __restrict__ g, const float* __restrict__ b)
{
    const int row  = blockIdx.x * 8 + (threadIdx.x >> 5);
    const int lane = threadIdx.x & 31;
    const float* xr = in + (size_t)row * EMB;

    float4 v[8];
    float s = 0.f;
    #pragma unroll
    for (int i = 0; i < 8; i++) {
        v[i] = *reinterpret_cast<const float4*>(xr + i * 128 + lane * 4);
        s += v[i].x + v[i].y + v[i].z + v[i].w;
    }
    #pragma unroll
    for (int o = 16; o; o >>= 1) s += __shfl_xor_sync(0xffffffffu, s, o);
    const float m = s * (1.f / EMB);

    float ss = 0.f;
    #pragma unroll
    for (int i = 0; i < 8; i++) {
        const float dx = v[i].x - m, dy = v[i].y - m, dz = v[i].z - m, dw = v[i].w - m;
        ss += dx * dx + dy * dy + dz * dz + dw * dw;
    }
    #pragma unroll
    for (int o = 16; o; o >>= 1) ss += __shfl_xor_sync(0xffffffffu, ss, o);
    const float r = rsqrtf(ss * (1.f / EMB) + 1e-5f);

    #pragma unroll
    for (int i = 0; i < 8; i++) {
        const int c0 = i * 128 + lane * 4;
        const float4 g4 = *reinterpret_cast<const float4*>(g + c0);
        const float4 b4 = *reinterpret_cast<const float4*>(b + c0);
        const float ox = (v[i].x - m) * r * g4.x + b4.x;
        const float oy = (v[i].y - m) * r * g4.y + b4.y;
        const float oz = (v[i].z - m) * r * g4.z + b4.z;
        const float ow = (v[i].w - m) * r * g4.w + b4.w;
        const float hx = __bfloat162float(__float2bfloat16_rn(ox));
        const float hy = __bfloat162float(__float2bfloat16_rn(oy));
        const float hz = __bfloat162float(__float2bfloat16_rn(oz));
        const float hw = __bfloat162float(__float2bfloat16_rn(ow));
        uint32_t hp[2], lp[2];
        hp[0] = pack_bf16(ox, oy);  hp[1] = pack_bf16(oz, ow);
        lp[0] = pack_bf16(ox - hx, oy - hy);
        lp[1] = pack_bf16(oz - hz, ow - hw);
        *reinterpret_cast<uint2*>(ohi + (size_t)row * EMB + c0) = *reinterpret_cast<uint2*>(hp);
        *reinterpret_cast<uint2*>(olo + (size_t)row * EMB + c0) = *reinterpret_cast<uint2*>(lp);
    }
}

// ---------------- smem geometry shared by both GEMMs ----------------
constexpr int MAT3 = 128 * 64;          // 8192 bytes per matrix per stage
constexpr int STG3 = 4 * MAT3;          // 32768
constexpr int GEMM_SMEM = 3 * STG3;     // 98304

// ---------------- bf16x3 GEMM: 128x128 tile, 8 warps (32x64 warp tile) — small GEMMs ----------------
template<bool BIAS, bool RELU, bool RES, bool SPLIT>
__global__ __launch_bounds__(256, 2) void mma_gemm(
    const __nv_bfloat16* __restrict__ Ahi, const __nv_bfloat16* __restrict__ Alo,
    const __nv_bfloat16* __restrict__ Bhi, const __nv_bfloat16* __restrict__ Blo,
    const float* __restrict__ bias, const float* __restrict__ res,
    float* __restrict__ C,
    __nv_bfloat16* __restrict__ Chi, __nv_bfloat16* __restrict__ Clo,
    int N, int K, int ntn, int ntiles)
{
    extern __shared__ char sm[];
    const int tid  = threadIdx.x;
    const int lane = tid & 31, wid = tid >> 5;
    const int wm = wid >> 1, wn = wid & 1;
    const uint32_t smb = smem_u32(sm);
    const int NC = K >> 5;

    const int rA = lane & 15, cA = lane >> 4;
    uint32_t offA[2];
    #pragma unroll
    for (int i = 0; i < 2; i++) {
        const int row = wm * 32 + i * 16 + rA;
        offA[i] = (uint32_t)(row * 64 + ((cA ^ ((row >> 1) & 3)) * 16));
    }
    const int rB = (lane & 7) | ((lane >> 4) << 3), cB = (lane >> 3) & 1;
    uint32_t offB[4];
    #pragma unroll
    for (int j = 0; j < 4; j++) {
        const int row = wn * 64 + j * 16 + rB;
        offB[j] = (uint32_t)(row * 64 + ((cB ^ ((row >> 1) & 3)) * 16));
    }

    const int lrow0 = tid >> 2,           lc0 = tid & 3;
    const int lrow1 = (tid + 256) >> 2,   lc1 = (tid + 256) & 3;
    const uint32_t lso0 = (uint32_t)(lrow0 * 64 + ((lc0 ^ ((lrow0 >> 1) & 3)) * 16));
    const uint32_t lso1 = (uint32_t)(lrow1 * 64 + ((lc1 ^ ((lrow1 >> 1) & 3)) * 16));

    const int g2 = lane >> 2, t2 = lane & 3;

    for (int t = blockIdx.x; t < ntiles; t += gridDim.x) {
        const int bm0 = (t / ntn) * 128;
        const int bn0 = (t % ntn) * 128;

        float acc[2][8][4];
        #pragma unroll
        for (int i = 0; i < 2; i++)
            #pragma unroll
            for (int j = 0; j < 8; j++)
                #pragma unroll
                for (int q = 0; q < 4; q++) acc[i][j][q] = 0.f;

        auto issue = [&](int c) {
            const int k0 = c << 5;
            const uint32_t st = smb + (c % 3) * STG3;
            {
                const size_t ga = (size_t)(bm0 + lrow0) * K + k0 + lc0 * 8;
                const size_t gb = (size_t)(bn0 + lrow0) * K + k0 + lc0 * 8;
                cp16(st + lso0,            Ahi + ga);
                cp16(st + MAT3 + lso0,     Alo + ga);
                cp16(st + 2 * MAT3 + lso0, Bhi + gb);
                cp16(st + 3 * MAT3 + lso0, Blo + gb);
            }
            {
                const size_t ga = (size_t)(bm0 + lrow1) * K + k0 + lc1 * 8;
                const size_t gb = (size_t)(bn0 + lrow1) * K + k0 + lc1 * 8;
                cp16(st + lso1,            Ahi + ga);
                cp16(st + MAT3 + lso1,     Alo + ga);
                cp16(st + 2 * MAT3 + lso1, Bhi + gb);
                cp16(st + 3 * MAT3 + lso1, Blo + gb);
            }
            cp_commit();
        };

        issue(0);
        issue(1);

        for (int c = 0; c < NC; c++) {
            if (c + 2 < NC) cp_wait1(); else cp_wait0();
            __syncthreads();
            if (c + 2 < NC) issue(c + 2);

            const uint32_t st = smb + (c % 3) * STG3;
            #pragma unroll
            for (int ks = 0; ks < 2; ks++) {
                const uint32_t kx = ks * 32;
                uint32_t ah[2][4], al[2][4];
                #pragma unroll
                for (int i = 0; i < 2; i++) {
                    ldm_x4(ah[i], st + (offA[i] ^ kx));
                    ldm_x4(al[i], st + MAT3 + (offA[i] ^ kx));
                }
                #pragma unroll
                for (int j4 = 0; j4 < 4; j4++) {
                    uint32_t bh[4], bl[4];
                    ldm_x4(bh, st + 2 * MAT3 + (offB[j4] ^ kx));
                    ldm_x4(bl, st + 3 * MAT3 + (offB[j4] ^ kx));
                    #pragma unroll
                    for (int i = 0; i < 2; i++)
                        #pragma unroll
                        for (int jj = 0; jj < 2; jj++) {
                            const int j = j4 * 2 + jj, hh = jj * 2;
                            mma16816(acc[i][j], ah[i], &bh[hh]);
                            mma16816(acc[i][j], ah[i], &bl[hh]);
                            mma16816(acc[i][j], al[i], &bh[hh]);
                        }
                }
            }
        }

        #pragma unroll
        for (int i = 0; i < 2; i++) {
            #pragma unroll
            for (int j = 0; j < 8; j++) {
                const int row0 = bm0 + wm * 32 + i * 16 + g2;
                const int col  = bn0 + wn * 64 + j * 8 + t2 * 2;
                #pragma unroll
                for (int half = 0; half < 2; half++) {
                    const int row = row0 + half * 8;
                    float vx = acc[i][j][half * 2 + 0];
                    float vy = acc[i][j][half * 2 + 1];
                    if (BIAS) { vx += bias[col]; vy += bias[col + 1]; }
                    if (RES) {
                        const float2 rr = *reinterpret_cast<const float2*>(res + (size_t)row * N + col);
                        vx += rr.x; vy += rr.y;
                    }
                    if (RELU) { vx = fmaxf(vx, 0.f); vy = fmaxf(vy, 0.f); }
                    if (SPLIT) {
                        float hx = __bfloat162float(__float2bfloat16_rn(vx));
                        float hy = __bfloat162float(__float2bfloat16_rn(vy));
                        *reinterpret_cast<uint32_t*>(Chi + (size_t)row * N + col) = pack_bf16(vx, vy);
                        *reinterpret_cast<uint32_t*>(Clo + (size_t)row * N + col) = pack_bf16(vx - hx, vy - hy);
                    } else {
                        float2 v; v.x = vx; v.y = vy;
                        *reinterpret_cast<float2*>(C + (size_t)row * N + col) = v;
                    }
                }
            }
        }
        __syncthreads();
    }
}

// ---------------- bf16x3 GEMM: 128x128 tile, 4 warps (64x64 warp tile) — big GEMMs ----------------
// Halves LDSM bytes per MMA (smem:tensor 0.67:1). 2 CTAs/SM, 256 regs/thread budget.
template<bool BIAS, bool RELU, bool SPLIT>
__global__ __launch_bounds__(128, 2) void mma_gemm_big(
    const __nv_bfloat16* __restrict__ Ahi, const __nv_bfloat16* __restrict__ Alo,
    const __nv_bfloat16* __restrict__ Bhi, const __nv_bfloat16* __restrict__ Blo,
    const float* __restrict__ bias,
    float* __restrict__ C,
    __nv_bfloat16* __restrict__ Chi, __nv_bfloat16* __restrict__ Clo,
    int N, int K, int ntn, int ntiles)
{
    extern __shared__ char sm[];
    const int tid  = threadIdx.x;
    const int lane = tid & 31, wid = tid >> 5;   // 4 warps
    const int wm = wid >> 1, wn = wid & 1;       // 2 x 2, warp tile 64x64
    const uint32_t smb = smem_u32(sm);
    const int NC = K >> 5;

    const int rA = lane & 15, cA = lane >> 4;
    uint32_t offA[4];
    #pragma unroll
    for (int i = 0; i < 4; i++) {
        const int row = wm * 64 + i * 16 + rA;
        offA[i] = (uint32_t)(row * 64 + ((cA ^ ((row >> 1) & 3)) * 16));
    }
    const int rB = (lane & 7) | ((lane >> 4) << 3), cB = (lane >> 3) & 1;
    uint32_t offB[4];
    #pragma unroll
    for (int j = 0; j < 4; j++) {
        const int row = wn * 64 + j * 16 + rB;
        offB[j] = (uint32_t)(row * 64 + ((cB ^ ((row >> 1) & 3)) * 16));
    }

    const int g2 = lane >> 2, t2 = lane & 3;

    for (int t = blockIdx.x; t < ntiles; t += gridDim.x) {
        const int bm0 = (t / ntn) * 128;
        const int bn0 = (t % ntn) * 128;

        float acc[4][8][4];
        #pragma unroll
        for (int i = 0; i < 4; i++)
            #pragma unroll
            for (int j = 0; j < 8; j++)
                #pragma unroll
                for (int q = 0; q < 4; q++) acc[i][j][q] = 0.f;

        auto issue = [&](int c) {
            const int k0 = c << 5;
            const uint32_t st = smb + (c % 3) * STG3;
            #pragma unroll
            for (int it = 0; it < 4; it++) {
                const int idx = tid + it * 128;
                const int row = idx >> 2, cc = idx & 3;
                const uint32_t so = (uint32_t)(row * 64 + ((cc ^ ((row >> 1) & 3)) * 16));
                const size_t ga = (size_t)(bm0 + row) * K + k0 + cc * 8;
                const size_t gb = (size_t)(bn0 + row) * K + k0 + cc * 8;
                cp16(st + so,            Ahi + ga);
                cp16(st + MAT3 + so,     Alo + ga);
                cp16(st + 2 * MAT3 + so, Bhi + gb);
                cp16(st + 3 * MAT3 + so, Blo + gb);
            }
            cp_commit();
        };

        issue(0);
        issue(1);

        for (int c = 0; c < NC; c++) {
            if (c + 2 < NC) cp_wait1(); else cp_wait0();
            __syncthreads();
            if (c + 2 < NC) issue(c + 2);

            const uint32_t st = smb + (c % 3) * STG3;
            #pragma unroll
            for (int ks = 0; ks < 2; ks++) {
                const uint32_t kx = ks * 32;
                uint32_t ah[4][4], al[4][4];
                #pragma unroll
                for (int i = 0; i < 4; i++) {
                    ldm_x4(ah[i], st + (offA[i] ^ kx));
                    ldm_x4(al[i], st + MAT3 + (offA[i] ^ kx));
                }
                #pragma unroll
                for (int j4 = 0; j4 < 4; j4++) {
                    uint32_t bh[4], bl[4];
                    ldm_x4(bh, st + 2 * MAT3 + (offB[j4] ^ kx));
                    ldm_x4(bl, st + 3 * MAT3 + (offB[j4] ^ kx));
                    #pragma unroll
                    for (int i = 0; i < 4; i++)
                        #pragma unroll
                        for (int jj = 0; jj < 2; jj++) {
                            const int j = j4 * 2 + jj, hh = jj * 2;
                            mma16816(acc[i][j], ah[i], &bh[hh]);
                            mma16816(acc[i][j], ah[i], &bl[hh]);
                            mma16816(acc[i][j], al[i], &bh[hh]);
                        }
                }
            }
        }

        #pragma unroll
        for (int i = 0; i < 4; i++) {
            #pragma unroll
            for (int j = 0; j < 8; j++) {
                const int row0 = bm0 + wm * 64 + i * 16 + g2;
                const int col  = bn0 + wn * 64 + j * 8 + t2 * 2;
                #pragma unroll
                for (int half = 0; half < 2; half++) {
                    const int row = row0 + half * 8;
                    float vx = acc[i][j][half * 2 + 0];
                    float vy = acc[i][j][half * 2 + 1];
                    if (BIAS) { vx += bias[col]; vy += bias[col + 1]; }
                    if (RELU) { vx = fmaxf(vx, 0.f); vy = fmaxf(vy, 0.f); }
                    if (SPLIT) {
                        float hx = __bfloat162float(__float2bfloat16_rn(vx));
                        float hy = __bfloat162float(__float2bfloat16_rn(vy));
                        *reinterpret_cast<uint32_t*>(Chi + (size_t)row * N + col) = pack_bf16(vx, vy);
                        *reinterpret_cast<uint32_t*>(Clo + (size_t)row * N + col) = pack_bf16(vx - hx, vy - hy);
                    } else {
                        float2 v; v.x = vx; v.y = vy;
                        *reinterpret_cast<float2*>(C + (size_t)row * N + col) = v;
                    }
                }
            }
        }
        __syncthreads();
    }
}

// ---------------- tensor-core flash attention (bf16x3, causal), packed QKV ----------------
constexpr int AP = 72;
constexpr int AQ_HI = 0;
constexpr int AQ_LO = 128 * AP;
constexpr int AST0  = 2 * 128 * AP;
constexpr int AMAT  = 64 * AP;
constexpr int ASTAGE = 4 * AMAT;
constexpr int ATTN_SMEM = (AST0 + 2 * ASTAGE) * 2;   // 110,592 bytes

__global__ __launch_bounds__(128) void attn_tc_kernel(
    const __nv_bfloat16* __restrict__ QKVh, const __nv_bfloat16* __restrict__ QKVl,
    __nv_bfloat16* __restrict__ Ohi, __nv_bfloat16* __restrict__ Olo)
{
    extern __shared__ __nv_bfloat16 smb16[];
    const uint32_t smb = smem_u32(smb16);

    const int qt = gridDim.x - 1 - blockIdx.x;
    const int bh = blockIdx.y;
    const int b  = bh >> 4;
    const int h  = bh & 15;
    const int tid = threadIdx.x;
    const int lane = tid & 31, wid = tid >> 5;
    const int g2 = lane >> 2, t2 = lane & 3;

    const size_t rowbase = (size_t)(b * SEQ + qt * 128);
    const int hoff = h * 64;

    #pragma unroll
    for (int it = 0; it < 8; it++) {
        int idx = tid + it * 128;
        int row = idx >> 3, c8 = (idx & 7) * 8;
        const size_t gq = (rowbase + row) * QKV + hoff + c8;
        *reinterpret_cast<uint4*>(smb16 + AQ_HI + row * AP + c8) =
            *reinterpret_cast<const uint4*>(QKVh + gq);
        *reinterpret_cast<uint4*>(smb16 + AQ_LO + row * AP + c8) =
            *reinterpret_cast<const uint4*>(QKVl + gq);
    }

    auto issue_kv = [&](int jt) {
        const uint32_t st = smb + (AST0 + (jt & 1) * ASTAGE) * 2;
        const size_t kb = (size_t)(b * SEQ + jt * 64);
        #pragma unroll
        for (int it = 0; it < 4; it++) {
            int idx = tid + it * 128;
            int row = idx >> 3, c8 = (idx & 7) * 8;
            const size_t g = (kb + row) * QKV + hoff + c8;
            const uint32_t so = (uint32_t)((row * AP + c8) * 2);
            cp16(st + so,            QKVh + g + EMB);
            cp16(st + AMAT * 2 + so, QKVl + g + EMB);
            cp16(st + AMAT * 4 + so, QKVh + g + 2 * EMB);
            cp16(st + AMAT * 6 + so, QKVl + g + 2 * EMB);
        }
        cp_commit();
    };

    const int rA = lane & 15, cA = lane >> 4;
    uint32_t qoff[2];
    #pragma unroll
    for (int i = 0; i < 2; i++)
        qoff[i] = (uint32_t)(((wid * 32 + i * 16 + rA) * AP + cA * 8) * 2);
    const int rB = (lane & 7) | ((lane >> 4) << 3), cB = (lane >> 3) & 1;
    uint32_t koff[4];
    #pragma unroll
    for (int j = 0; j < 4; j++)
        koff[j] = (uint32_t)(((j * 16 + rB) * AP + cB * 8) * 2);
    const uint32_t voff_row = (uint32_t)(rA * AP + cA * 8) * 2;

    float oacc[2][8][4];
    float mstat[4], lstat[4];
    #pragma unroll
    for (int i = 0; i < 2; i++)
        #pragma unroll
        for (int j = 0; j < 8; j++)
            #pragma unroll
            for (int q = 0; q < 4; q++) oacc[i][j][q] = 0.f;
    #pragma unroll
    for (int t = 0; t < 4; t++) { mstat[t] = -1e30f; lstat[t] = 0.f; }

    const int NT = 2 * qt + 2;
    issue_kv(0);

    for (int jt = 0; jt < NT; jt++) {
        if (jt + 1 < NT) { issue_kv(jt + 1); cp_wait1(); }
        else cp_wait0();
        __syncthreads();

        const uint32_t st = smb + (AST0 + (jt & 1) * ASTAGE) * 2;

        float sacc[2][8][4];
        #pragma unroll
        for (int i = 0; i < 2; i++)
            #pragma unroll
            for (int j = 0; j < 8; j++)
                #pragma unroll
                for (int q = 0; q < 4; q++) sacc[i][j][q] = 0.f;

        #pragma unroll
        for (int ks = 0; ks < 4; ks++) {
            const uint32_t kadd = ks * 32;
            uint32_t qh[2][4], ql[2][4], kh[4][4], kl[4][4];
            #pragma unroll
            for (int i = 0; i < 2; i++) {
                ldm_x4(qh[i], smb + AQ_HI * 2 + qoff[i] + kadd);
                ldm_x4(ql[i], smb + AQ_LO * 2 + qoff[i] + kadd);
            }
            #pragma unroll
            for (int j = 0; j < 4; j++) {
                ldm_x4(kh[j], st + koff[j] + kadd);
                ldm_x4(kl[j], st + AMAT * 2 + koff[j] + kadd);
            }
            #pragma unroll
            for (int i = 0; i < 2; i++)
                #pragma unroll
                for (int j = 0; j < 8; j++) {
                    const int j4 = j >> 1, hh = (j & 1) * 2;
                    mma16816(sacc[i][j], qh[i], &kh[j4][hh]);
                    mma16816(sacc[i][j], qh[i], &kl[j4][hh]);
                    mma16816(sacc[i][j], ql[i], &kh[j4][hh]);
                }
        }

        const bool need_mask = (jt * 64 + 63) > (qt * 128);
        #pragma unroll
        for (int i = 0; i < 2; i++) {
            #pragma unroll
            for (int j = 0; j < 8; j++) {
                #pragma unroll
                for (int q = 0; q < 4; q++) {
                    float s = sacc[i][j][q] * 0.125f;
                    if (need_mask) {
                        const int row = qt * 128 + wid * 32 + i * 16 + g2 + (q >> 1) * 8;
                        const int col = jt * 64 + j * 8 + t2 * 2 + (q & 1);
                        if (col > row) s = -1e30f;
                    }
                    sacc[i][j][q] = s;
                }
            }
        }

        float alpha[4];
        #pragma unroll
        for (int i = 0; i < 2; i++) {
            #pragma unroll
            for (int half = 0; half < 2; half++) {
                const int t = i * 2 + half;
                float mx = -1e30f;
                #pragma unroll
                for (int j = 0; j < 8; j++)
                    mx = fmaxf(mx, fmaxf(sacc[i][j][half * 2], sacc[i][j][half * 2 + 1]));
                mx = fmaxf(mx, __shfl_xor_sync(0xffffffffu, mx, 1));
                mx = fmaxf(mx, __shfl_xor_sync(0xffffffffu, mx, 2));
                const float mnew = fmaxf(mstat[t], mx);
                alpha[t] = exp2f((mstat[t] - mnew) * 1.4426950408889634f);
                mstat[t] = mnew;
                float rs = 0.f;
                #pragma unroll
                for (int j = 0; j < 8; j++) {
                    float p0 = exp2f((sacc[i][j][half * 2]     - mnew) * 1.4426950408889634f);
                    float p1 = exp2f((sacc[i][j][half * 2 + 1] - mnew) * 1.4426950408889634f);
                    sacc[i][j][half * 2] = p0;
                    sacc[i][j][half * 2 + 1] = p1;
                    rs += p0 + p1;
                }
                rs += __shfl_xor_sync(0xffffffffu, rs, 1);
                rs += __shfl_xor_sync(0xffffffffu, rs, 2);
                lstat[t] = lstat[t] * alpha[t] + rs;
                #pragma unroll
                for (int j = 0; j < 8; j++) {
                    oacc[i][j][half * 2]     *= alpha[t];
                    oacc[i][j][half * 2 + 1] *= alpha[t];
                }
            }
        }

        #pragma unroll
        for (int kk = 0; kk < 4; kk++) {
            uint32_t ph[2][4], pl[2][4];
            #pragma unroll
            for (int i = 0; i < 2; i++) {
                const int j0 = 2 * kk, j1 = j0 + 1;
                const float c0 = sacc[i][j0][0], c1 = sacc[i][j0][1];
                const float c2 = sacc[i][j0][2], c3 = sacc[i][j0][3];
                const float d0 = sacc[i][j1][0], d1 = sacc[i][j1][1];
                const float d2 = sacc[i][j1][2], d3 = sacc[i][j1][3];
                ph[i][0] = pack_bf16(c0, c1);
                ph[i][1] = pack_bf16(c2, c3);
                ph[i][2] = pack_bf16(d0, d1);
                ph[i][3] = pack_bf16(d2, d3);
                const float h0 = __bfloat162float(__float2bfloat16_rn(c0));
                const float h1 = __bfloat162float(__float2bfloat16_rn(c1));
                const float h2 = __bfloat162float(__float2bfloat16_rn(c2));
                const float h3 = __bfloat162float(__float2bfloat16_rn(c3));
                const float e0 = __bfloat162float(__float2bfloat16_rn(d0));
                const float e1 = __bfloat162float(__float2bfloat16_rn(d1));
                const float e2 = __bfloat162float(__float2bfloat16_rn(d2));
                const float e3 = __bfloat162float(__float2bfloat16_rn(d3));
                pl[i][0] = pack_bf16(c0 - h0, c1 - h1);
                pl[i][1] = pack_bf16(c2 - h2, c3 - h3);
                pl[i][2] = pack_bf16(d0 - e0, d1 - e1);
                pl[i][3] = pack_bf16(d2 - e2, d3 - e3);
            }
            uint32_t vh[4][4], vl[4][4];
            const uint32_t vrow = (uint32_t)((kk * 16) * AP * 2);
            #pragma unroll
            for (int dgrp = 0; dgrp < 4; dgrp++) {
                const uint32_t va = st + AMAT * 4 + vrow + voff_row + (uint32_t)(dgrp * 16 * 2);
                ldm_x4t(vh[dgrp], va);
                ldm_x4t(vl[dgrp], va + AMAT * 2);
            }
            #pragma unroll
            for (int i = 0; i < 2; i++)
                #pragma unroll
                for (int jd = 0; jd < 8; jd++) {
                    const int vg = jd >> 1, sel = (jd & 1) * 2;
                    mma16816(oacc[i][jd], ph[i], &vh[vg][sel]);
                    mma16816(oacc[i][jd], ph[i], &vl[vg][sel]);
                    mma16816(oacc[i][jd], pl[i], &vh[vg][sel]);
                }
        }
        __syncthreads();
    }

    #pragma unroll
    for (int i = 0; i < 2; i++) {
        #pragma unroll
        for (int half = 0; half < 2; half++) {
            const int t = i * 2 + half;
            const float inv = 1.f / lstat[t];
            const size_t row = rowbase + wid * 32 + i * 16 + g2 + half * 8;
            #pragma unroll
            for (int jd = 0; jd < 8; jd++) {
                const int col = hoff + jd * 8 + t2 * 2;
                const float vx = oacc[i][jd][half * 2]     * inv;
                const float vy = oacc[i][jd][half * 2 + 1] * inv;
                const float hx = __bfloat162float(__float2bfloat16_rn(vx));
                const float hy = __bfloat162float(__float2bfloat16_rn(vy));
                *reinterpret_cast<uint32_t*>(Ohi + row * EMB + col) = pack_bf16(vx, vy);
                *reinterpret_cast<uint32_t*>(Olo + row * EMB + col) = pack_bf16(vx - hx, vy - hy);
            }
        }
    }
}

// ---------------- host orchestration ----------------
static inline int gclamp2(int ntiles) { return ntiles < 296 ? ntiles : 296; }

extern "C" void kernel_launch(void* const* d_in, const int* in_sizes, int n_in,
                              void* d_out, int out_size)
{
    const int*   idx  = (const int*)  d_in[0];
    const float* tok  = (const float*)d_in[1];
    const float* pos  = (const float*)d_in[2];
    const float* Wq   = (const float*)d_in[3];
    const float* Wk   = (const float*)d_in[4];
    const float* Wv   = (const float*)d_in[5];
    const float* Wo   = (const float*)d_in[6];
    const float* bo   = (const float*)d_in[7];
    const float* W1   = (const float*)d_in[8];
    const float* b1   = (const float*)d_in[9];
    const float* W2   = (const float*)d_in[10];
    const float* b2   = (const float*)d_in[11];
    const float* ln1g = (const float*)d_in[12];
    const float* ln1b = (const float*)d_in[13];
    const float* ln2g = (const float*)d_in[14];
    const float* ln2b = (const float*)d_in[15];
    const float* lnfg = (const float*)d_in[16];
    const float* lnfb = (const float*)d_in[17];
    const float* lmb  = (const float*)d_in[18];
    float* out = (float*)d_out;

    float* x;
    __nv_bfloat16 *whi, *wlo, *tokhi, *toklo;
    __nv_bfloat16 *ahi, *alo, *qkvh, *qkvl, *ohi, *olo, *fhi, *flo;
    cudaGetSymbolAddress((void**)&x,  g_x);
    cudaGetSymbolAddress((void**)&whi, g_Whi);
    cudaGetSymbolAddress((void**)&wlo, g_Wlo);
    cudaGetSymbolAddress((void**)&tokhi, g_tokhi);
    cudaGetSymbolAddress((void**)&toklo, g_toklo);
    cudaGetSymbolAddress((void**)&ahi, g_ahi);
    cudaGetSymbolAddress((void**)&alo, g_alo);
    cudaGetSymbolAddress((void**)&qkvh, g_qkvh);
    cudaGetSymbolAddress((void**)&qkvl, g_qkvl);
    cudaGetSymbolAddress((void**)&ohi, g_ohi);
    cudaGetSymbolAddress((void**)&olo, g_olo);
    cudaGetSymbolAddress((void**)&fhi, g_fhi);
    cudaGetSymbolAddress((void**)&flo, g_flo);

    cudaFuncSetAttribute(attn_tc_kernel, cudaFuncAttributeMaxDynamicSharedMemorySize, ATTN_SMEM);
    cudaFuncSetAttribute(mma_gemm<true,false,true,false>,  cudaFuncAttributeMaxDynamicSharedMemorySize, GEMM_SMEM);
    cudaFuncSetAttribute(mma_gemm_big<false,false,true>, cudaFuncAttributeMaxDynamicSharedMemorySize, GEMM_SMEM);
    cudaFuncSetAttribute(mma_gemm_big<true,true,true>,   cudaFuncAttributeMaxDynamicSharedMemorySize, GEMM_SMEM);
    cudaFuncSetAttribute(mma_gemm_big<true,false,false>, cudaFuncAttributeMaxDynamicSharedMemorySize, GEMM_SMEM);

    // [0] merged weight + tok conversion
    conv_all_kernel<<<CONV_BLKS, 256>>>(Wq, Wk, Wv, Wo, W1, W2, tok,
                                        whi, wlo, tokhi, toklo);
    // [1] embedding
    embed_kernel<<<(MROWS * EMB) / 256, 256>>>(x, idx, tok, pos);

    const int ntQKV = (MROWS / 128) * (QKV / 128);     // 384
    const int ntE   = (MROWS / 128) * (EMB / 128);     // 128
    const int ntF   = (MROWS / 128) * (DFF / 128);     // 512
    const int ntV   = (MROWS / 128) * (VOC / 128);     // 4000
    const dim3 gattn(SEQ / 128, BSZ * NH);

    for (int l = 0; l < LAY; l++) {
        const size_t wb = (size_t)l * WPL;
        ln_split_kernel<<<MROWS / 8, 256>>>(ahi, alo, x, ln1g + (size_t)l * EMB, ln1b + (size_t)l * EMB);
        mma_gemm_big<false,false,true><<<gclamp2(ntQKV), 128, GEMM_SMEM>>>(
            ahi, alo, whi + wb + OFF_WQ, wlo + wb + OFF_WQ, nullptr,
            nullptr, qkvh, qkvl, QKV, EMB, QKV / 128, ntQKV);
        attn_tc_kernel<<<gattn, 128, ATTN_SMEM>>>(qkvh, qkvl, ohi, olo);
        mma_gemm<true,false,true,false><<<gclamp2(ntE), 256, GEMM_SMEM>>>(
            ohi, olo, whi + wb + OFF_WO, wlo + wb + OFF_WO, bo + (size_t)l * EMB, x, x,
            nullptr, nullptr, EMB, EMB, EMB / 128, ntE);
        ln_split_kernel<<<MROWS / 8, 256>>>(ahi, alo, x, ln2g + (size_t)l * EMB, ln2b + (size_t)l * EMB);
        mma_gemm_big<true,true,true><<<gclamp2(ntF), 128, GEMM_SMEM>>>(
            ahi, alo, whi + wb + OFF_W1, wlo + wb + OFF_W1, b1 + (size_t)l * DFF,
            nullptr, fhi, flo, DFF, EMB, DFF / 128, ntF);
        mma_gemm<true,false,true,false><<<gclamp2(ntE), 256, GEMM_SMEM>>>(
            fhi, flo, whi + wb + OFF_W2, wlo + wb + OFF_W2, b2 + (size_t)l * EMB, x, x,
            nullptr, nullptr, EMB, DFF, EMB / 128, ntE);
    }

    ln_split_kernel<<<MROWS / 8, 256>>>(ahi, alo, x, lnfg, lnfb);
    mma_gemm_big<true,false,false><<<gclamp2(ntV), 128, GEMM_SMEM>>>(
        ahi, alo, tokhi, toklo, lmb,
        out, nullptr, nullptr, VOC, EMB, VOC / 128, ntV);
}